// round 2
// baseline (speedup 1.0000x reference)
#include <cuda_runtime.h>

#define B_ 64
#define S_ 2048
#define I_ 128
#define H_ 512
#define O_ 128

// ---------------- scratch (device globals: no allocations allowed) ----------
__device__ float g_xin[(size_t)B_ * S_ * H_];   // input projection (B,S,H)
__device__ float g_hs [(size_t)B_ * S_ * H_];   // hidden states   (B,S,H)

// ---------------- f32x2 helpers ---------------------------------------------
__device__ __forceinline__ unsigned long long ffma2(unsigned long long a,
                                                    unsigned long long b,
                                                    unsigned long long c) {
    unsigned long long d;
    asm("fma.rn.f32x2 %0, %1, %2, %3;" : "=l"(d) : "l"(a), "l"(b), "l"(c));
    return d;
}
__device__ __forceinline__ unsigned long long pack2(float x, float y) {
    unsigned long long p;
    asm("mov.b64 %0, {%1, %2};" : "=l"(p) : "f"(x), "f"(y));
    return p;
}
__device__ __forceinline__ float2 unpack2(unsigned long long p) {
    float2 r;
    asm("mov.b64 {%0, %1}, %2;" : "=f"(r.x), "=f"(r.y) : "l"(p));
    return r;
}
__device__ __forceinline__ unsigned smem_u32(const void* p) {
    unsigned a;
    asm("{ .reg .u64 t; cvta.to.shared.u64 t, %1; cvt.u32.u64 %0, t; }"
        : "=r"(a) : "l"(p));
    return a;
}
__device__ __forceinline__ unsigned ctarank() {
    unsigned r; asm("mov.u32 %0, %%cluster_ctarank;" : "=r"(r)); return r;
}
__device__ __forceinline__ void cluster_sync() {
    asm volatile("barrier.cluster.arrive.aligned;" ::: "memory");
    asm volatile("barrier.cluster.wait.aligned;" ::: "memory");
}

// ---------------- tiled fp32 GEMM:  C[M,N] = A[M,K] @ B[N,K]^T + bias --------
// 128x128 block tile, 256 threads, 8x8 per-thread register tile.
template <int N, int K, bool SRC_HS, bool DST_XIN>
__global__ __launch_bounds__(256) void gemm_kernel(const float* __restrict__ Ap,
                                                   const float* __restrict__ Bm,
                                                   const float* __restrict__ bias,
                                                   float* __restrict__ Cp) {
    __shared__ __align__(16) float Ast[32][132];
    __shared__ __align__(16) float Bst[32][132];
    const float* A = SRC_HS ? g_hs : Ap;
    float* C = DST_XIN ? g_xin : Cp;

    const int tid = threadIdx.x;
    const int bm = blockIdx.x, bn = blockIdx.y;
    const float* Ab = A + (size_t)bm * 128 * K;
    const float* Bb = Bm + (size_t)bn * 128 * K;

    const int tx = tid & 15, ty = tid >> 4;
    float acc[8][8] = {};

    for (int k0 = 0; k0 < K; k0 += 32) {
#pragma unroll
        for (int u = 0; u < 4; u++) {
            int idx4 = tid + u * 256;          // 0..1023 -> 128 rows x 8 float4
            int m = idx4 >> 3;
            int kq = (idx4 & 7) * 4;
            float4 va = *(const float4*)&Ab[(size_t)m * K + k0 + kq];
            Ast[kq + 0][m] = va.x; Ast[kq + 1][m] = va.y;
            Ast[kq + 2][m] = va.z; Ast[kq + 3][m] = va.w;
            float4 vb = *(const float4*)&Bb[(size_t)m * K + k0 + kq];
            Bst[kq + 0][m] = vb.x; Bst[kq + 1][m] = vb.y;
            Bst[kq + 2][m] = vb.z; Bst[kq + 3][m] = vb.w;
        }
        __syncthreads();
#pragma unroll
        for (int kc = 0; kc < 32; kc++) {
            float4 a0 = *(const float4*)&Ast[kc][ty * 8];
            float4 a1 = *(const float4*)&Ast[kc][ty * 8 + 4];
            float4 b0 = *(const float4*)&Bst[kc][tx * 8];
            float4 b1 = *(const float4*)&Bst[kc][tx * 8 + 4];
            float a[8] = {a0.x, a0.y, a0.z, a0.w, a1.x, a1.y, a1.z, a1.w};
            float b[8] = {b0.x, b0.y, b0.z, b0.w, b1.x, b1.y, b1.z, b1.w};
#pragma unroll
            for (int i = 0; i < 8; i++)
#pragma unroll
                for (int j = 0; j < 8; j++) acc[i][j] += a[i] * b[j];
        }
        __syncthreads();
    }
#pragma unroll
    for (int i = 0; i < 8; i++) {
        size_t m = (size_t)bm * 128 + ty * 8 + i;
#pragma unroll
        for (int j = 0; j < 8; j++) {
            int n = bn * 128 + tx * 8 + j;
            C[m * N + n] = acc[i][j] + bias[n];
        }
    }
}

// ---------------- recurrent scan (8-CTA cluster per batch-group) -------------
// cluster = 8 CTAs = 8 output-slices (64 cols each) of one batch-group (4 b).
// W_rec slice in registers. h exchanged via DSMEM: producer writes its 256-
// float slice to a double-buffered local stage; after barrier.cluster each
// warp-pair pulls its K-slice straight from peer kg's stage (rank == kg).
__global__ __launch_bounds__(512, 1) __cluster_dims__(8, 1, 1)
void scan_kernel(const float* __restrict__ h0,
                 const float* __restrict__ Wrec,
                 float* __restrict__ hfinal) {
    __shared__ __align__(16) float h_s[4 * H_];     // [b][k]   8 KB
    __shared__ __align__(16) float stage[2][4][64]; // parity,[b][jl]  2 KB
    __shared__ float red[8][4][64];                 // [kg][b][jl]  8 KB

    const int tid = threadIdx.x;
    const int bg = blockIdx.x >> 3;                 // batch-group 0..15
    const unsigned rank = ctarank();                // 0..7 = output slice
    const int w = tid >> 5, lane = tid & 31;
    const int kg = w >> 1;                          // 0..7 -> 64-wide K slice
    const int jl = ((w & 1) << 5) | lane;           // 0..63 local output col
    const int jg = (int)rank * 64 + jl;             // global output col
    const int k0 = kg * 64;
    const int p = tid & 63;                         // id within warp-pair

    // ---- W_rec[jg][k0..k0+63] into registers as 32 f32x2 pairs
    unsigned long long Wr[32];
    {
        const float4* wp = (const float4*)&Wrec[(size_t)jg * H_ + k0];
#pragma unroll
        for (int i = 0; i < 16; i++) {
            float4 v = wp[i];
            Wr[2 * i]     = pack2(v.x, v.y);
            Wr[2 * i + 1] = pack2(v.z, v.w);
        }
    }

    // ---- remote pull address (peer kg's stage, this pair's slice)
    const unsigned stage_base = smem_u32(&stage[0][0][0]);
    unsigned pull_remote;     // addr of stage[0][b][c4*4] on peer kg
    {
        unsigned local = stage_base + (unsigned)((p >> 4) * 256 + (p & 15) * 16);
        asm("mapa.shared::cluster.u32 %0, %1, %2;"
            : "=r"(pull_remote) : "r"(local), "r"((unsigned)kg));
    }
    float* h_dst = &h_s[(p >> 4) * H_ + k0 + (p & 15) * 4];

    // ---- reducer identity (first 256 threads): (rb, rj)
    const int rb = tid >> 6;
    const int rj = tid & 63;
    float xr = 0.f;
    size_t xin_base = 0;
    if (tid < 256) {
        xin_base = ((size_t)(bg * 4 + rb) * S_) * H_ + (size_t)rank * 64 + rj;
        xr = g_xin[xin_base];
    }

    // ---- t=0: full h0 load
    ((float4*)h_s)[tid] = ((const float4*)(h0 + (size_t)bg * 4 * H_))[tid];
    __syncthreads();

    for (int t = 0; t < S_; t++) {
        // ---- partial GEMM over our 64-wide K slice (f32x2)
        unsigned long long acc0 = 0, acc1 = 0, acc2 = 0, acc3 = 0;
        {
            const ulonglong2* hp0 = (const ulonglong2*)&h_s[0 * H_ + k0];
            const ulonglong2* hp1 = (const ulonglong2*)&h_s[1 * H_ + k0];
            const ulonglong2* hp2 = (const ulonglong2*)&h_s[2 * H_ + k0];
            const ulonglong2* hp3 = (const ulonglong2*)&h_s[3 * H_ + k0];
#pragma unroll
            for (int i = 0; i < 16; i++) {
                ulonglong2 u0 = hp0[i];
                acc0 = ffma2(Wr[2 * i], u0.x, acc0);
                acc0 = ffma2(Wr[2 * i + 1], u0.y, acc0);
                ulonglong2 u1 = hp1[i];
                acc1 = ffma2(Wr[2 * i], u1.x, acc1);
                acc1 = ffma2(Wr[2 * i + 1], u1.y, acc1);
                ulonglong2 u2 = hp2[i];
                acc2 = ffma2(Wr[2 * i], u2.x, acc2);
                acc2 = ffma2(Wr[2 * i + 1], u2.y, acc2);
                ulonglong2 u3 = hp3[i];
                acc3 = ffma2(Wr[2 * i], u3.x, acc3);
                acc3 = ffma2(Wr[2 * i + 1], u3.y, acc3);
            }
        }
        float2 a0 = unpack2(acc0), a1 = unpack2(acc1);
        float2 a2 = unpack2(acc2), a3 = unpack2(acc3);
        red[kg][0][jl] = a0.x + a0.y;
        red[kg][1][jl] = a1.x + a1.y;
        red[kg][2][jl] = a2.x + a2.y;
        red[kg][3][jl] = a3.x + a3.y;
        __syncthreads();

        // ---- reduce over 8 K-slices, add xin, tanh, publish slice to stage
        const int nxt = (t + 1) & 1;
        if (tid < 256) {
            float s = xr;
#pragma unroll
            for (int q = 0; q < 8; q++) s += red[q][rb][rj];
            float hn = tanhf(s);
            int bglob = bg * 4 + rb;
            stage[nxt][rb][rj] = hn;                 // local slice for peers
            g_hs[((size_t)bglob * S_ + t) * H_ + rank * 64 + rj] = hn;
            if (t == S_ - 1) hfinal[(size_t)bglob * H_ + rank * 64 + rj] = hn;
            else xr = g_xin[xin_base + (size_t)(t + 1) * H_];  // prefetch
        }

        // ---- cluster barrier: release our stage writes, acquire peers'
        cluster_sync();

        // ---- pull next h: our K slice comes exactly from peer kg's stage
        if (t + 1 < S_) {
            float4 v;
            asm volatile("ld.shared::cluster.v4.f32 {%0,%1,%2,%3}, [%4];"
                         : "=f"(v.x), "=f"(v.y), "=f"(v.z), "=f"(v.w)
                         : "r"(pull_remote + (unsigned)(nxt * 1024)));
            *(float4*)h_dst = v;
            __syncthreads();
        }
    }
}

// ---------------- launch ------------------------------------------------------
extern "C" void kernel_launch(void* const* d_in, const int* in_sizes, int n_in,
                              void* d_out, int out_size) {
    const float* inputs  = (const float*)d_in[0];
    const float* h0      = (const float*)d_in[1];
    const float* W_in_w  = (const float*)d_in[2];
    const float* W_in_b  = (const float*)d_in[3];
    const float* W_rec_w = (const float*)d_in[4];
    const float* W_out_w = (const float*)d_in[5];
    const float* W_out_b = (const float*)d_in[6];

    float* out    = (float*)d_out;                      // (B,S,O)
    float* hfinal = out + (size_t)B_ * S_ * O_;         // (B,H)

    // 1) xin = inputs @ W_in^T + b   -> g_xin
    {
        dim3 grid(B_ * S_ / 128, H_ / 128);
        gemm_kernel<H_, I_, false, true><<<grid, 256>>>(inputs, W_in_w, W_in_b, nullptr);
    }
    // 2) sequential scan: 16 clusters x 8 CTAs, all co-resident
    scan_kernel<<<128, 512>>>(h0, W_rec_w, hfinal);

    // 3) outputs = hs @ W_out^T + b  -> d_out
    {
        dim3 grid(B_ * S_ / 128, O_ / 128);
        gemm_kernel<O_, H_, true, false><<<grid, 256>>>(nullptr, W_out_w, W_out_b, out);
    }
}

// round 3
// speedup vs baseline: 1.3251x; 1.3251x over previous
#include <cuda_runtime.h>

#define B_ 64
#define S_ 2048
#define I_ 128
#define H_ 512
#define O_ 128

// ---------------- scratch (device globals: no allocations allowed) ----------
__device__ float g_xin[(size_t)B_ * S_ * H_];   // input projection (B,S,H)
__device__ float g_hs [(size_t)B_ * S_ * H_];   // hidden states   (B,S,H)

// ---------------- helpers ----------------------------------------------------
__device__ __forceinline__ unsigned long long ffma2(unsigned long long a,
                                                    unsigned long long b,
                                                    unsigned long long c) {
    unsigned long long d;
    asm("fma.rn.f32x2 %0, %1, %2, %3;" : "=l"(d) : "l"(a), "l"(b), "l"(c));
    return d;
}
__device__ __forceinline__ unsigned long long pack2(float x, float y) {
    unsigned long long p;
    asm("mov.b64 %0, {%1, %2};" : "=l"(p) : "f"(x), "f"(y));
    return p;
}
__device__ __forceinline__ float2 unpack2(unsigned long long p) {
    float2 r;
    asm("mov.b64 {%0, %1}, %2;" : "=f"(r.x), "=f"(r.y) : "l"(p));
    return r;
}
__device__ __forceinline__ unsigned smem_u32(const void* p) {
    unsigned a;
    asm("{ .reg .u64 t; cvta.to.shared.u64 t, %1; cvt.u32.u64 %0, t; }"
        : "=r"(a) : "l"(p));
    return a;
}
__device__ __forceinline__ unsigned ctarank() {
    unsigned r; asm("mov.u32 %0, %%cluster_ctarank;" : "=r"(r)); return r;
}
__device__ __forceinline__ unsigned mapa_u32(unsigned addr, unsigned rank) {
    unsigned r;
    asm("mapa.shared::cluster.u32 %0, %1, %2;" : "=r"(r) : "r"(addr), "r"(rank));
    return r;
}
__device__ __forceinline__ void mbar_init(unsigned a, unsigned cnt) {
    asm volatile("mbarrier.init.shared.b64 [%0], %1;" :: "r"(a), "r"(cnt) : "memory");
}
__device__ __forceinline__ void mbar_expect(unsigned a, unsigned bytes) {
    asm volatile("mbarrier.arrive.expect_tx.shared.b64 _, [%0], %1;"
                 :: "r"(a), "r"(bytes) : "memory");
}
__device__ __forceinline__ void mbar_wait(unsigned a, unsigned parity) {
    unsigned done;
    asm volatile(
        "{\n\t.reg .pred p;\n\t"
        "mbarrier.try_wait.parity.acquire.cta.shared::cta.b64 p, [%1], %2;\n\t"
        "selp.b32 %0, 1, 0, p;\n\t}"
        : "=r"(done) : "r"(a), "r"(parity) : "memory");
    if (!done) {
        asm volatile(
            "{\n\t.reg .pred P1;\n\t"
            "WL_%=:\n\t"
            "mbarrier.try_wait.parity.acquire.cta.shared::cta.b64 P1, [%0], %1, 0x989680;\n\t"
            "@P1 bra.uni WD_%=;\n\t"
            "bra.uni WL_%=;\n\t"
            "WD_%=:\n\t}"
            :: "r"(a), "r"(parity) : "memory");
    }
}
__device__ __forceinline__ void bulk_push(unsigned dst_remote, unsigned src_local,
                                          unsigned bytes, unsigned mbar_remote) {
    asm volatile(
        "cp.async.bulk.shared::cluster.shared::cta.mbarrier::complete_tx::bytes "
        "[%0], [%1], %2, [%3];"
        :: "r"(dst_remote), "r"(src_local), "r"(bytes), "r"(mbar_remote) : "memory");
}

// ---------------- tiled fp32 GEMM:  C[M,N] = A[M,K] @ B[N,K]^T + bias --------
// 128x128 block tile, 256 threads, 8x8 per-thread tile, f32x2 FMA (2 rows/op).
template <int N, int K, bool SRC_HS, bool DST_XIN>
__global__ __launch_bounds__(256) void gemm_kernel(const float* __restrict__ Ap,
                                                   const float* __restrict__ Bm,
                                                   const float* __restrict__ bias,
                                                   float* __restrict__ Cp) {
    __shared__ __align__(16) float Ast[32][132];
    __shared__ __align__(16) float Bst[32][132];
    const float* A = SRC_HS ? g_hs : Ap;
    float* C = DST_XIN ? g_xin : Cp;

    const int tid = threadIdx.x;
    const int bm = blockIdx.x, bn = blockIdx.y;
    const float* Ab = A + (size_t)bm * 128 * K;
    const float* Bb = Bm + (size_t)bn * 128 * K;

    const int tx = tid & 15, ty = tid >> 4;
    unsigned long long acc2[4][8];
#pragma unroll
    for (int i = 0; i < 4; i++)
#pragma unroll
        for (int j = 0; j < 8; j++) acc2[i][j] = 0ull;

    for (int k0 = 0; k0 < K; k0 += 32) {
#pragma unroll
        for (int u = 0; u < 4; u++) {
            int idx4 = tid + u * 256;          // 0..1023 -> 128 rows x 8 float4
            int m = idx4 >> 3;
            int kq = (idx4 & 7) * 4;
            float4 va = *(const float4*)&Ab[(size_t)m * K + k0 + kq];
            Ast[kq + 0][m] = va.x; Ast[kq + 1][m] = va.y;
            Ast[kq + 2][m] = va.z; Ast[kq + 3][m] = va.w;
            float4 vb = *(const float4*)&Bb[(size_t)m * K + k0 + kq];
            Bst[kq + 0][m] = vb.x; Bst[kq + 1][m] = vb.y;
            Bst[kq + 2][m] = vb.z; Bst[kq + 3][m] = vb.w;
        }
        __syncthreads();
#pragma unroll
        for (int kc = 0; kc < 32; kc++) {
            float4 a0 = *(const float4*)&Ast[kc][ty * 8];
            float4 a1 = *(const float4*)&Ast[kc][ty * 8 + 4];
            float4 b0 = *(const float4*)&Bst[kc][tx * 8];
            float4 b1 = *(const float4*)&Bst[kc][tx * 8 + 4];
            unsigned long long A2[4] = {pack2(a0.x, a0.y), pack2(a0.z, a0.w),
                                        pack2(a1.x, a1.y), pack2(a1.z, a1.w)};
            float bb[8] = {b0.x, b0.y, b0.z, b0.w, b1.x, b1.y, b1.z, b1.w};
#pragma unroll
            for (int j = 0; j < 8; j++) {
                unsigned long long B2 = pack2(bb[j], bb[j]);
#pragma unroll
                for (int i = 0; i < 4; i++) acc2[i][j] = ffma2(A2[i], B2, acc2[i][j]);
            }
        }
        __syncthreads();
    }
#pragma unroll
    for (int i = 0; i < 4; i++) {
        size_t m0 = (size_t)bm * 128 + ty * 8 + 2 * i;
#pragma unroll
        for (int j = 0; j < 8; j++) {
            int n = bn * 128 + tx * 8 + j;
            float2 v = unpack2(acc2[i][j]);
            C[m0 * N + n]       = v.x + bias[n];
            C[(m0 + 1) * N + n] = v.y + bias[n];
        }
    }
}

// ---------------- recurrent scan: 8-CTA cluster, mbarrier push pipeline ------
// cluster = 8 CTAs = 8 output-slices (64 cols) of one batch-group (4 batches).
// Per step each CTA pushes its 1KB h-slice into all 8 peers' h buffer (layout
// [slice][b][64]) via cp.async.bulk smem->smem, signaling the peer's mbarrier
// (complete_tx). Triple-buffered h + 3 mbarriers; expect posted one step ahead.
__global__ __launch_bounds__(512, 1) __cluster_dims__(8, 1, 1)
void scan_kernel(const float* __restrict__ h0,
                 const float* __restrict__ Wrec,
                 float* __restrict__ hfinal) {
    __shared__ __align__(16) float h_s2[3][8][4][64];   // 24 KB, [buf][slice][b][c]
    __shared__ __align__(16) float stage[2][4][64];     // 2 KB producer stage
    __shared__ float red[8][4][64];                     // 8 KB partial sums
    __shared__ __align__(8) unsigned long long mbar[3];

    const int tid = threadIdx.x;
    const int bg = blockIdx.x >> 3;                 // batch-group 0..15
    const unsigned rank = ctarank();                // 0..7 = output slice
    const int w = tid >> 5, lane = tid & 31;
    const int kg = w >> 1;                          // 0..7 -> 64-wide K slice
    const int jl = ((w & 1) << 5) | lane;           // 0..63 local output col
    const int jg = (int)rank * 64 + jl;             // global output col

    const unsigned mb = smem_u32(&mbar[0]);
    const unsigned hbase = smem_u32(&h_s2[0][0][0][0]);
    const unsigned stbase = smem_u32(&stage[0][0][0]);

    // ---- W_rec[jg][kg*64 .. +63] into 32 f32x2 register pairs
    unsigned long long Wr[32];
    {
        const float4* wp = (const float4*)&Wrec[(size_t)jg * H_ + kg * 64];
#pragma unroll
        for (int i = 0; i < 16; i++) {
            float4 v = wp[i];
            Wr[2 * i]     = pack2(v.x, v.y);
            Wr[2 * i + 1] = pack2(v.z, v.w);
        }
    }

    // ---- mbarrier init + pre-loop expect for step-0 pushes (buffer 1)
    if (tid == 0) {
        mbar_init(mb + 0, 1);
        mbar_init(mb + 8, 1);
        mbar_init(mb + 16, 1);
        asm volatile("fence.proxy.async.shared::cta;" ::: "memory");
        mbar_expect(mb + 8, 8192);
    }

    // ---- h0 -> h_s2[0] with [slice][b][c] layout
    {
        int lin = tid * 4;
        int s = lin >> 8, b = (lin >> 6) & 3, c = lin & 63;
        *(float4*)&h_s2[0][s][b][c] =
            *(const float4*)&h0[(size_t)(bg * 4 + b) * H_ + s * 64 + c];
    }
    __syncthreads();
    // one-time cluster barrier: all peers' mbar init/expect + h0 ready
    asm volatile("barrier.cluster.arrive.aligned;" ::: "memory");
    asm volatile("barrier.cluster.wait.aligned;" ::: "memory");

    // ---- reducer identity (first 256 threads): (rb, rj)
    const int rb = tid >> 6;
    const int rj = tid & 63;
    float xr = 0.f;
    size_t xin_base = 0;
    if (tid < 256) {
        xin_base = ((size_t)(bg * 4 + rb) * S_) * H_ + (size_t)rank * 64 + rj;
        xr = g_xin[xin_base];
    }

    unsigned p0 = 0, p1 = 0, p2 = 0;   // per-mbar phase parities

    for (int t = 0; t < S_; t++) {
        const int cur = t % 3;

        // expect for pushes that will arrive during step t+1 (buffer (t+2)%3)
        if (tid == 0 && t + 2 < S_) mbar_expect(mb + ((t + 2) % 3) * 8, 8192);

        // ---- partial GEMM over our 64-wide K slice (f32x2, broadcast LDS)
        unsigned long long acc0 = 0, acc1 = 0, acc2v = 0, acc3 = 0;
        {
            const ulonglong2* hp0 = (const ulonglong2*)&h_s2[cur][kg][0][0];
            const ulonglong2* hp1 = (const ulonglong2*)&h_s2[cur][kg][1][0];
            const ulonglong2* hp2 = (const ulonglong2*)&h_s2[cur][kg][2][0];
            const ulonglong2* hp3 = (const ulonglong2*)&h_s2[cur][kg][3][0];
#pragma unroll
            for (int i = 0; i < 16; i++) {
                ulonglong2 u0 = hp0[i];
                acc0 = ffma2(Wr[2 * i], u0.x, acc0);
                acc0 = ffma2(Wr[2 * i + 1], u0.y, acc0);
                ulonglong2 u1 = hp1[i];
                acc1 = ffma2(Wr[2 * i], u1.x, acc1);
                acc1 = ffma2(Wr[2 * i + 1], u1.y, acc1);
                ulonglong2 u2 = hp2[i];
                acc2v = ffma2(Wr[2 * i], u2.x, acc2v);
                acc2v = ffma2(Wr[2 * i + 1], u2.y, acc2v);
                ulonglong2 u3 = hp3[i];
                acc3 = ffma2(Wr[2 * i], u3.x, acc3);
                acc3 = ffma2(Wr[2 * i + 1], u3.y, acc3);
            }
        }
        float2 a0 = unpack2(acc0), a1 = unpack2(acc1);
        float2 a2 = unpack2(acc2v), a3 = unpack2(acc3);
        red[kg][0][jl] = a0.x + a0.y;
        red[kg][1][jl] = a1.x + a1.y;
        red[kg][2][jl] = a2.x + a2.y;
        red[kg][3][jl] = a3.x + a3.y;
        __syncthreads();

        // ---- reduce 8 K-slices, add xin, tanh, write stage + g_hs
        if (tid < 256) {
            float s = xr;
#pragma unroll
            for (int q = 0; q < 8; q++) s += red[q][rb][rj];
            float hn = tanhf(s);
            int bglob = bg * 4 + rb;
            stage[t & 1][rb][rj] = hn;
            g_hs[((size_t)bglob * S_ + t) * H_ + rank * 64 + rj] = hn;
            if (t == S_ - 1) hfinal[(size_t)bglob * H_ + rank * 64 + rj] = hn;
            else xr = g_xin[xin_base + (size_t)(t + 1) * H_];   // prefetch
        }
        __syncthreads();

        // ---- push our slice to all 8 peers (incl. self), then wait
        if (t + 1 < S_) {
            const int nb = (t + 1) % 3;
            if (tid < 8) {
                asm volatile("fence.proxy.async.shared::cta;" ::: "memory");
                unsigned src = stbase + (unsigned)((t & 1) * 1024);
                unsigned dstl = hbase + (unsigned)(nb * 8192 + (int)rank * 1024);
                unsigned dstr = mapa_u32(dstl, (unsigned)tid);
                unsigned mbr = mapa_u32(mb + (unsigned)(nb * 8), (unsigned)tid);
                bulk_push(dstr, src, 1024, mbr);
            }
            if (nb == 0)      { mbar_wait(mb + 0, p0);  p0 ^= 1; }
            else if (nb == 1) { mbar_wait(mb + 8, p1);  p1 ^= 1; }
            else              { mbar_wait(mb + 16, p2); p2 ^= 1; }
        }
    }
}

// ---------------- launch ------------------------------------------------------
extern "C" void kernel_launch(void* const* d_in, const int* in_sizes, int n_in,
                              void* d_out, int out_size) {
    const float* inputs  = (const float*)d_in[0];
    const float* h0      = (const float*)d_in[1];
    const float* W_in_w  = (const float*)d_in[2];
    const float* W_in_b  = (const float*)d_in[3];
    const float* W_rec_w = (const float*)d_in[4];
    const float* W_out_w = (const float*)d_in[5];
    const float* W_out_b = (const float*)d_in[6];

    float* out    = (float*)d_out;                      // (B,S,O)
    float* hfinal = out + (size_t)B_ * S_ * O_;         // (B,H)

    // 1) xin = inputs @ W_in^T + b   -> g_xin
    {
        dim3 grid(B_ * S_ / 128, H_ / 128);
        gemm_kernel<H_, I_, false, true><<<grid, 256>>>(inputs, W_in_w, W_in_b, nullptr);
    }
    // 2) sequential scan: 16 clusters x 8 CTAs, mbarrier push pipeline
    scan_kernel<<<128, 512>>>(h0, W_rec_w, hfinal);

    // 3) outputs = hs @ W_out^T + b  -> d_out
    {
        dim3 grid(B_ * S_ / 128, O_ / 128);
        gemm_kernel<O_, H_, true, false><<<grid, 256>>>(nullptr, W_out_w, W_out_b, out);
    }
}